// round 1
// baseline (speedup 1.0000x reference)
#include <cuda_runtime.h>
#include <math.h>

#define HIDDEN   2048
#define INTERDIM 8192

typedef unsigned long long u64;

// ------------------------------------------------------------------
// Device scratch (static allocation — no cudaMalloc allowed)
// ------------------------------------------------------------------
__device__ float g_gw[(size_t)INTERDIM * HIDDEN];   //  64 MiB  gate weight [I,H]
__device__ float g_uw[(size_t)INTERDIM * HIDDEN];   //  64 MiB  up weight   [I,H]
__device__ float g_dw[(size_t)HIDDEN * INTERDIM];   //  64 MiB  down weight [H,I]
__device__ float g_up[(size_t)8192 * INTERDIM];     // 256 MiB  up proj     [T,I]
__device__ float g_it[(size_t)8192 * INTERDIM];     // 256 MiB  inter       [T,I]

// ------------------------------------------------------------------
// Catmull-Rom spline reconstruction (matches numpy float64 grid +
// float32 blend of the reference exactly in structure)
// ------------------------------------------------------------------
__global__ void spline_kernel(const float* __restrict__ cp,
                              float* __restrict__ w,
                              int n_ctrl, long long n)
{
    long long j = (long long)blockIdx.x * blockDim.x + threadIdx.x;
    if (j >= n) return;

    double delta = (double)(n_ctrl - 1) / (double)(n - 1);
    double t = (j == n - 1) ? (double)(n_ctrl - 1) : (double)j * delta;

    long long i = (long long)floor(t);
    if (i < 0) i = 0;
    if (i > (long long)n_ctrl - 2) i = n_ctrl - 2;
    float f = (float)(t - (double)i);

    int i0 = (int)(i - 1 < 0 ? 0 : i - 1);
    int i1 = (int)i;
    int i2 = (int)(i + 1 > n_ctrl - 1 ? n_ctrl - 1 : i + 1);
    int i3 = (int)(i + 2 > n_ctrl - 1 ? n_ctrl - 1 : i + 2);

    float p0 = cp[i0], p1 = cp[i1], p2 = cp[i2], p3 = cp[i3];
    float f2 = f * f;
    float f3 = f2 * f;
    float val = 0.5f * (2.0f * p1
               + (p2 - p0) * f
               + (2.0f * p0 - 5.0f * p1 + 4.0f * p2 - p3) * f2
               + (3.0f * p1 - p0 - 3.0f * p2 + p3) * f3);
    w[j] = val;
}

// ------------------------------------------------------------------
// Packed f32x2 helpers (FFMA2: 2 FMA per issue slot — PTX-only path)
// ------------------------------------------------------------------
__device__ __forceinline__ u64 fma2(u64 a, u64 b, u64 c) {
    u64 d;
    asm("fma.rn.f32x2 %0, %1, %2, %3;" : "=l"(d) : "l"(a), "l"(b), "l"(c));
    return d;
}
__device__ __forceinline__ u64 dup2(float x) {
    u64 r;
    asm("mov.b64 %0, {%1, %1};" : "=l"(r) : "f"(x));
    return r;
}
__device__ __forceinline__ void unpack2(u64 v, float& x, float& y) {
    asm("mov.b64 {%0, %1}, %2;" : "=f"(x), "=f"(y) : "l"(v));
}

// ------------------------------------------------------------------
// NT GEMM:  C[M,N] = A[M,K] (row-major) * B[N,K]^T (row-major)
// 128x128 block tile, BK=16, 256 threads, 8x8 per-thread microtile
// EPI==1: C = silu(acc) * U   (fused SwiGLU gate epilogue)
// ------------------------------------------------------------------
template <int EPI>
__global__ void __launch_bounds__(256, 2)
gemm_nt(const float* __restrict__ A,
        const float* __restrict__ B,
        const float* __restrict__ U,
        float* __restrict__ C,
        int M, int N, int K)
{
    __shared__ __align__(16) float As[16][128];
    __shared__ __align__(16) float Bs[16][128];

    const int bm = blockIdx.y * 128;
    const int bn = blockIdx.x * 128;
    const int tid = threadIdx.x;
    const int tx = tid & 15;   // n direction (8 cols each)
    const int ty = tid >> 4;   // m direction (8 rows each)

    u64 acc[8][4];
#pragma unroll
    for (int i = 0; i < 8; i++)
#pragma unroll
        for (int j = 0; j < 4; j++) acc[i][j] = 0ull;

    for (int k0 = 0; k0 < K; k0 += 16) {
        // cooperative tile load: 512 float4 per operand, 2 per thread
#pragma unroll
        for (int l = 0; l < 2; l++) {
            int idx = tid + l * 256;
            int row = idx >> 2;            // 0..127
            int c4  = (idx & 3) * 4;       // 0,4,8,12
            float4 a = *(const float4*)&A[(long long)(bm + row) * K + k0 + c4];
            As[c4 + 0][row] = a.x; As[c4 + 1][row] = a.y;
            As[c4 + 2][row] = a.z; As[c4 + 3][row] = a.w;
            float4 b = *(const float4*)&B[(long long)(bn + row) * K + k0 + c4];
            Bs[c4 + 0][row] = b.x; Bs[c4 + 1][row] = b.y;
            Bs[c4 + 2][row] = b.z; Bs[c4 + 3][row] = b.w;
        }
        __syncthreads();

#pragma unroll
        for (int k = 0; k < 16; k++) {
            const float* ap = &As[k][ty * 8];
            float4 a0 = *(const float4*)(ap);
            float4 a1 = *(const float4*)(ap + 4);
            u64 ad[8];
            ad[0] = dup2(a0.x); ad[1] = dup2(a0.y);
            ad[2] = dup2(a0.z); ad[3] = dup2(a0.w);
            ad[4] = dup2(a1.x); ad[5] = dup2(a1.y);
            ad[6] = dup2(a1.z); ad[7] = dup2(a1.w);

            const u64* bp = (const u64*)&Bs[k][tx * 8];
            ulonglong2 bb0 = *(const ulonglong2*)(bp);
            ulonglong2 bb1 = *(const ulonglong2*)(bp + 2);
            u64 bd[4] = { bb0.x, bb0.y, bb1.x, bb1.y };

#pragma unroll
            for (int i = 0; i < 8; i++)
#pragma unroll
                for (int j = 0; j < 4; j++)
                    acc[i][j] = fma2(ad[i], bd[j], acc[i][j]);
        }
        __syncthreads();
    }

    // epilogue
    const int base_n = bn + tx * 8;
#pragma unroll
    for (int i = 0; i < 8; i++) {
        long long off = (long long)(bm + ty * 8 + i) * N + base_n;
        float v[8];
#pragma unroll
        for (int j = 0; j < 4; j++)
            unpack2(acc[i][j], v[2 * j], v[2 * j + 1]);
        if (EPI == 1) {
            float4 u0 = *(const float4*)&U[off];
            float4 u1 = *(const float4*)&U[off + 4];
            float uu[8] = { u0.x, u0.y, u0.z, u0.w, u1.x, u1.y, u1.z, u1.w };
#pragma unroll
            for (int jj = 0; jj < 8; jj++) {
                float c = v[jj];
                float s = c / (1.0f + expf(-c));
                v[jj] = s * uu[jj];
            }
        }
        float4 o0 = { v[0], v[1], v[2], v[3] };
        float4 o1 = { v[4], v[5], v[6], v[7] };
        *(float4*)&C[off]     = o0;
        *(float4*)&C[off + 4] = o1;
    }
}

// ------------------------------------------------------------------
// Launch
// ------------------------------------------------------------------
extern "C" void kernel_launch(void* const* d_in, const int* in_sizes, int n_in,
                              void* d_out, int out_size)
{
    (void)n_in; (void)out_size;
    const float* x   = (const float*)d_in[0];  // [4,2048,2048]
    const float* gcp = (const float*)d_in[1];
    const float* ucp = (const float*)d_in[2];
    const float* dcp = (const float*)d_in[3];
    float* out = (float*)d_out;

    const int M  = in_sizes[0] / HIDDEN;  // 8192 tokens
    const int ng = in_sizes[1];
    const int nu = in_sizes[2];
    const int nd = in_sizes[3];

    float *gw, *uw, *dw, *up, *it;
    cudaGetSymbolAddress((void**)&gw, g_gw);
    cudaGetSymbolAddress((void**)&uw, g_uw);
    cudaGetSymbolAddress((void**)&dw, g_dw);
    cudaGetSymbolAddress((void**)&up, g_up);
    cudaGetSymbolAddress((void**)&it, g_it);

    const long long NW = (long long)INTERDIM * HIDDEN;  // 16,777,216
    const int sb = (int)((NW + 255) / 256);
    spline_kernel<<<sb, 256>>>(gcp, gw, ng, NW);
    spline_kernel<<<sb, 256>>>(ucp, uw, nu, NW);
    spline_kernel<<<sb, 256>>>(dcp, dw, nd, NW);

    dim3 g1(INTERDIM / 128, M / 128);
    gemm_nt<0><<<g1, 256>>>(x, uw, nullptr, up, M, INTERDIM, HIDDEN);   // up = X @ Uw^T
    gemm_nt<1><<<g1, 256>>>(x, gw, up, it, M, INTERDIM, HIDDEN);        // it = silu(X@Gw^T)*up

    dim3 g2(HIDDEN / 128, M / 128);
    gemm_nt<0><<<g2, 256>>>(it, dw, nullptr, out, M, HIDDEN, INTERDIM); // out = it @ Dw^T
}

// round 3
// speedup vs baseline: 2.2980x; 2.2980x over previous
#include <cuda_runtime.h>
#include <cuda_bf16.h>
#include <stdint.h>
#include <math.h>

#define HID   2048
#define ITR   8192
#define MTOK  8192
#define NW ((size_t)ITR * (size_t)HID)

typedef uint32_t u32;

// ---------------------------------------------------------------
// Static device scratch (no cudaMalloc allowed)
// ---------------------------------------------------------------
__device__ __align__(256) __nv_bfloat16 g_xh[(size_t)MTOK * HID];
__device__ __align__(256) __nv_bfloat16 g_xl[(size_t)MTOK * HID];
__device__ __align__(256) __nv_bfloat16 g_gwh[NW];
__device__ __align__(256) __nv_bfloat16 g_gwl[NW];
__device__ __align__(256) __nv_bfloat16 g_uwh[NW];
__device__ __align__(256) __nv_bfloat16 g_uwl[NW];
__device__ __align__(256) __nv_bfloat16 g_dwh[NW];
__device__ __align__(256) __nv_bfloat16 g_dwl[NW];
__device__ __align__(256) __nv_bfloat16 g_ith[(size_t)MTOK * ITR];
__device__ __align__(256) __nv_bfloat16 g_itl[(size_t)MTOK * ITR];
__device__ __align__(256) float         g_up[(size_t)MTOK * ITR];

// ---------------------------------------------------------------
// PTX helpers (all baseline sm_80/sm_90 PTX — no 'a'-gated features)
// ---------------------------------------------------------------
__device__ __forceinline__ u32 smem_u32(const void* p) {
    u32 a;
    asm("{ .reg .u64 t; cvta.to.shared.u64 t, %1; cvt.u32.u64 %0, t; }" : "=r"(a) : "l"(p));
    return a;
}
__device__ __forceinline__ void cp16(u32 s, const void* g) {
    asm volatile("cp.async.cg.shared.global [%0], [%1], 16;" :: "r"(s), "l"(g) : "memory");
}
#define CP_COMMIT() asm volatile("cp.async.commit_group;" ::: "memory")
#define CP_WAIT(n)  asm volatile("cp.async.wait_group %0;" :: "n"(n) : "memory")

__device__ __forceinline__ void ldsm4(u32* r, u32 a) {
    asm volatile("ldmatrix.sync.aligned.m8n8.x4.shared.b16 {%0,%1,%2,%3}, [%4];"
                 : "=r"(r[0]), "=r"(r[1]), "=r"(r[2]), "=r"(r[3]) : "r"(a));
}
__device__ __forceinline__ void ldsm2(u32* r, u32 a) {
    asm volatile("ldmatrix.sync.aligned.m8n8.x2.shared.b16 {%0,%1}, [%2];"
                 : "=r"(r[0]), "=r"(r[1]) : "r"(a));
}
__device__ __forceinline__ void mma16816(float* d, const u32* a, const u32* b) {
    asm volatile("mma.sync.aligned.m16n8k16.row.col.f32.bf16.bf16.f32 "
                 "{%0,%1,%2,%3}, {%4,%5,%6,%7}, {%8,%9}, {%0,%1,%2,%3};"
                 : "+f"(d[0]), "+f"(d[1]), "+f"(d[2]), "+f"(d[3])
                 : "r"(a[0]), "r"(a[1]), "r"(a[2]), "r"(a[3]), "r"(b[0]), "r"(b[1]));
}

// ---------------------------------------------------------------
// Preprocessing
// ---------------------------------------------------------------
__device__ __forceinline__ void split2(float v, __nv_bfloat16& h, __nv_bfloat16& l) {
    h = __float2bfloat16_rn(v);
    l = __float2bfloat16_rn(v - __bfloat162float(h));
}

__global__ void xsplit_kernel(const float* __restrict__ x,
                              __nv_bfloat16* __restrict__ xh,
                              __nv_bfloat16* __restrict__ xl, long long n)
{
    long long j = (long long)blockIdx.x * blockDim.x + threadIdx.x;
    if (j >= n) return;
    split2(x[j], xh[j], xl[j]);
}

__global__ void spline_split_kernel(const float* __restrict__ cp,
                                    __nv_bfloat16* __restrict__ wh,
                                    __nv_bfloat16* __restrict__ wl,
                                    int n_ctrl, long long n)
{
    long long j = (long long)blockIdx.x * blockDim.x + threadIdx.x;
    if (j >= n) return;

    double delta = (double)(n_ctrl - 1) / (double)(n - 1);
    double t = (j == n - 1) ? (double)(n_ctrl - 1) : (double)j * delta;

    long long i = (long long)floor(t);
    if (i < 0) i = 0;
    if (i > (long long)n_ctrl - 2) i = n_ctrl - 2;
    float f = (float)(t - (double)i);

    int i0 = (int)(i - 1 < 0 ? 0 : i - 1);
    int i1 = (int)i;
    int i2 = (int)(i + 1 > n_ctrl - 1 ? n_ctrl - 1 : i + 1);
    int i3 = (int)(i + 2 > n_ctrl - 1 ? n_ctrl - 1 : i + 2);

    float p0 = cp[i0], p1 = cp[i1], p2 = cp[i2], p3 = cp[i3];
    float f2 = f * f;
    float f3 = f2 * f;
    float val = 0.5f * (2.0f * p1
               + (p2 - p0) * f
               + (2.0f * p0 - 5.0f * p1 + 4.0f * p2 - p3) * f2
               + (3.0f * p1 - p0 - 3.0f * p2 + p3) * f3);
    split2(val, wh[j], wl[j]);
}

// ---------------------------------------------------------------
// Tensor-core NT GEMM via mma.sync (bf16, fp32 acc), split-bf16
// 3-pass: acc += Ah*Bh + Ah*Bl + Al*Bh
// Block 128x128, BK=32, 8 warps (2M x 4N), warp tile 64x32.
// 4-stage cp.async pipeline. smem rows padded to 80B (conflict-free).
// EPI 0: C fp32.  EPI 1: SwiGLU — C=silu(acc)*U, write bf16 hi/lo.
// ---------------------------------------------------------------
#define ROWB   80                    // padded smem row bytes (32 bf16 = 64B + 16B pad)
#define TILEB  (128 * ROWB)          // 10240 B per operand tile
#define NS     4
#define STAGEB (4 * TILEB)           // Ah, Al, Bh, Bl

template <int EPI>
__global__ void __launch_bounds__(256, 1)
gemm_mma(const __nv_bfloat16* __restrict__ Ah_,
         const __nv_bfloat16* __restrict__ Al_,
         const __nv_bfloat16* __restrict__ Bh_,
         const __nv_bfloat16* __restrict__ Bl_,
         float* __restrict__ Cf,
         const float* __restrict__ Uf,
         __nv_bfloat16* __restrict__ Oh,
         __nv_bfloat16* __restrict__ Ol,
         int N, int K)
{
    extern __shared__ __align__(128) char sm[];
    const u32 sb = smem_u32(sm);
    const int tid  = threadIdx.x;
    const int lane = tid & 31;
    const int wid  = tid >> 5;
    const int wm   = wid & 1;        // 0..1 : 64-row slice
    const int wn   = wid >> 1;       // 0..3 : 32-col slice
    const int bm   = blockIdx.y * 128;
    const int bn   = blockIdx.x * 128;
    const int NC   = K >> 5;

    float acc[4][4][4];
#pragma unroll
    for (int mi = 0; mi < 4; mi++)
#pragma unroll
        for (int ni = 0; ni < 4; ni++)
#pragma unroll
            for (int q = 0; q < 4; q++) acc[mi][ni][q] = 0.0f;

    // per-thread load coords (2 chunks of 16B per operand tile)
    const int r0 = tid >> 2;                 // row for chunk 0 (0..63)
    const int r1 = (tid + 256) >> 2;         // row for chunk 1 (64..127)
    const int c0 = (tid & 3) * 8;            // k offset in halves
    const int c1 = c0;                       // same pattern

    auto issue_stage = [&](int stg) {
        const u32 base = sb + (u32)(stg % NS) * STAGEB;
        const int k0 = stg * 32;
        {
            const u32 so = base + (u32)r0 * ROWB + (u32)(c0 >> 3) * 16;
            const size_t ga = (size_t)(bm + r0) * K + k0 + c0;
            const size_t gb = (size_t)(bn + r0) * K + k0 + c0;
            cp16(so + 0 * TILEB, Ah_ + ga);
            cp16(so + 1 * TILEB, Al_ + ga);
            cp16(so + 2 * TILEB, Bh_ + gb);
            cp16(so + 3 * TILEB, Bl_ + gb);
        }
        {
            const u32 so = base + (u32)r1 * ROWB + (u32)(c1 >> 3) * 16;
            const size_t ga = (size_t)(bm + r1) * K + k0 + c1;
            const size_t gb = (size_t)(bn + r1) * K + k0 + c1;
            cp16(so + 0 * TILEB, Ah_ + ga);
            cp16(so + 1 * TILEB, Al_ + ga);
            cp16(so + 2 * TILEB, Bh_ + gb);
            cp16(so + 3 * TILEB, Bl_ + gb);
        }
    };

    // prologue: stages 0..NS-2
#pragma unroll
    for (int s = 0; s < NS - 1; s++) {
        if (s < NC) issue_stage(s);
        CP_COMMIT();
    }

    const int alr = lane & 15;               // ldmatrix A row-in-tile
    const int alc = (lane >> 4) << 3;        // 0 or 8 (k half)
    const int blr = lane & 7;                // ldmatrix B row-in-tile
    const int blc = ((lane >> 3) & 1) << 3;  // 0 or 8 (k half)

    for (int c = 0; c < NC; c++) {
        const int pf = c + NS - 1;
        if (pf < NC) issue_stage(pf);
        CP_COMMIT();
        CP_WAIT(NS - 1);
        __syncthreads();

        const u32 stb = sb + (u32)(c % NS) * STAGEB;

#pragma unroll
        for (int ks = 0; ks < 2; ks++) {
            u32 ah[4][4], al[4][4];
#pragma unroll
            for (int mi = 0; mi < 4; mi++) {
                const u32 ra = stb + (u32)(wm * 64 + mi * 16 + alr) * ROWB
                             + (u32)(ks * 16 + alc) * 2;
                ldsm4(ah[mi], ra);
                ldsm4(al[mi], ra + TILEB);
            }
            u32 bh[4][2], bl[4][2];
#pragma unroll
            for (int ni = 0; ni < 4; ni++) {
                const u32 rb = stb + 2 * TILEB
                             + (u32)(wn * 32 + ni * 8 + blr) * ROWB
                             + (u32)(ks * 16 + blc) * 2;
                ldsm2(bh[ni], rb);
                ldsm2(bl[ni], rb + TILEB);
            }
#pragma unroll
            for (int mi = 0; mi < 4; mi++)
#pragma unroll
                for (int ni = 0; ni < 4; ni++) {
                    mma16816(acc[mi][ni], ah[mi], bh[ni]);
                    mma16816(acc[mi][ni], ah[mi], bl[ni]);
                    mma16816(acc[mi][ni], al[mi], bh[ni]);
                }
        }
        __syncthreads();
    }

    // ---------------- epilogue ----------------
    const int er = lane >> 2;
    const int ec = (lane & 3) * 2;
#pragma unroll
    for (int mi = 0; mi < 4; mi++) {
#pragma unroll
        for (int ni = 0; ni < 4; ni++) {
            const int row = bm + wm * 64 + mi * 16 + er;
            const int col = bn + wn * 32 + ni * 8 + ec;
            const float* d = acc[mi][ni];
            if (EPI == 0) {
                *(float2*)&Cf[(size_t)row * N + col] = make_float2(d[0], d[1]);
                *(float2*)&Cf[(size_t)(row + 8) * N + col] = make_float2(d[2], d[3]);
            } else {
#pragma unroll
                for (int h = 0; h < 2; h++) {
                    const int rr = row + h * 8;
                    const size_t off = (size_t)rr * N + col;
                    float2 uu = *(const float2*)&Uf[off];
                    float g0 = d[h * 2 + 0], g1 = d[h * 2 + 1];
                    float v0 = (g0 / (1.0f + expf(-g0))) * uu.x;
                    float v1 = (g1 / (1.0f + expf(-g1))) * uu.y;
                    __nv_bfloat16 h0, l0, h1, l1;
                    split2(v0, h0, l0);
                    split2(v1, h1, l1);
                    u32 ph = (u32)__bfloat16_as_ushort(h0) |
                             ((u32)__bfloat16_as_ushort(h1) << 16);
                    u32 pl = (u32)__bfloat16_as_ushort(l0) |
                             ((u32)__bfloat16_as_ushort(l1) << 16);
                    *(u32*)&Oh[off] = ph;
                    *(u32*)&Ol[off] = pl;
                }
            }
        }
    }
}

// ---------------------------------------------------------------
// Launch
// ---------------------------------------------------------------
extern "C" void kernel_launch(void* const* d_in, const int* in_sizes, int n_in,
                              void* d_out, int out_size)
{
    (void)n_in; (void)out_size;
    const float* x   = (const float*)d_in[0];
    const float* gcp = (const float*)d_in[1];
    const float* ucp = (const float*)d_in[2];
    const float* dcp = (const float*)d_in[3];
    float* out = (float*)d_out;

    const int M = in_sizes[0] / HID;   // 8192

    void *xh, *xl, *gwh, *gwl, *uwh, *uwl, *dwh, *dwl, *ith, *itl, *up;
    cudaGetSymbolAddress(&xh, g_xh);   cudaGetSymbolAddress(&xl, g_xl);
    cudaGetSymbolAddress(&gwh, g_gwh); cudaGetSymbolAddress(&gwl, g_gwl);
    cudaGetSymbolAddress(&uwh, g_uwh); cudaGetSymbolAddress(&uwl, g_uwl);
    cudaGetSymbolAddress(&dwh, g_dwh); cudaGetSymbolAddress(&dwl, g_dwl);
    cudaGetSymbolAddress(&ith, g_ith); cudaGetSymbolAddress(&itl, g_itl);
    cudaGetSymbolAddress(&up, g_up);

    // preprocessing
    long long nX = (long long)M * HID;
    xsplit_kernel<<<(int)((nX + 255) / 256), 256>>>(x, (__nv_bfloat16*)xh,
                                                    (__nv_bfloat16*)xl, nX);
    long long nw = (long long)NW;
    int sbk = (int)((nw + 255) / 256);
    spline_split_kernel<<<sbk, 256>>>(gcp, (__nv_bfloat16*)gwh, (__nv_bfloat16*)gwl,
                                      in_sizes[1], nw);
    spline_split_kernel<<<sbk, 256>>>(ucp, (__nv_bfloat16*)uwh, (__nv_bfloat16*)uwl,
                                      in_sizes[2], nw);
    spline_split_kernel<<<sbk, 256>>>(dcp, (__nv_bfloat16*)dwh, (__nv_bfloat16*)dwl,
                                      in_sizes[3], nw);

    const int SMEM = NS * STAGEB;   // 163840
    static bool attr_done = false;
    if (!attr_done) {
        cudaFuncSetAttribute(gemm_mma<0>, cudaFuncAttributeMaxDynamicSharedMemorySize, SMEM);
        cudaFuncSetAttribute(gemm_mma<1>, cudaFuncAttributeMaxDynamicSharedMemorySize, SMEM);
        attr_done = true;
    }

    dim3 g1(ITR / 128, M / 128);
    // up = X @ Uw^T  (fp32)
    gemm_mma<0><<<g1, 256, SMEM>>>((const __nv_bfloat16*)xh, (const __nv_bfloat16*)xl,
                                   (const __nv_bfloat16*)uwh, (const __nv_bfloat16*)uwl,
                                   (float*)up, nullptr, nullptr, nullptr, ITR, HID);
    // it = silu(X @ Gw^T) * up  -> bf16 hi/lo
    gemm_mma<1><<<g1, 256, SMEM>>>((const __nv_bfloat16*)xh, (const __nv_bfloat16*)xl,
                                   (const __nv_bfloat16*)gwh, (const __nv_bfloat16*)gwl,
                                   nullptr, (const float*)up,
                                   (__nv_bfloat16*)ith, (__nv_bfloat16*)itl, ITR, HID);
    // out = it @ Dw^T  (fp32)
    dim3 g2(HID / 128, M / 128);
    gemm_mma<0><<<g2, 256, SMEM>>>((const __nv_bfloat16*)ith, (const __nv_bfloat16*)itl,
                                   (const __nv_bfloat16*)dwh, (const __nv_bfloat16*)dwl,
                                   out, nullptr, nullptr, nullptr, HID, ITR);
}

// round 8
// speedup vs baseline: 3.0186x; 1.3136x over previous
#include <cuda_runtime.h>
#include <cuda_bf16.h>
#include <stdint.h>
#include <math.h>

#define HID   2048
#define ITR   8192
#define MTOK  8192
#define NW ((size_t)ITR * (size_t)HID)

typedef uint32_t u32;
typedef unsigned long long u64;

// ---------------------------------------------------------------
// Static device scratch (no cudaMalloc allowed)
// ---------------------------------------------------------------
__device__ __align__(256) __nv_bfloat16 g_xh[(size_t)MTOK * HID];
__device__ __align__(256) __nv_bfloat16 g_xl[(size_t)MTOK * HID];
__device__ __align__(256) __nv_bfloat16 g_gwh[NW];
__device__ __align__(256) __nv_bfloat16 g_gwl[NW];
__device__ __align__(256) __nv_bfloat16 g_uwh[NW];
__device__ __align__(256) __nv_bfloat16 g_uwl[NW];
__device__ __align__(256) __nv_bfloat16 g_dwh[NW];
__device__ __align__(256) __nv_bfloat16 g_dwl[NW];
__device__ __align__(256) __nv_bfloat16 g_ith[(size_t)MTOK * ITR];
__device__ __align__(256) __nv_bfloat16 g_itl[(size_t)MTOK * ITR];

// ---------------------------------------------------------------
// PTX helpers (baseline sm_80/90 PTX only — nothing 'a'-gated)
// ---------------------------------------------------------------
__device__ __forceinline__ u32 smem_u32(const void* p) {
    u32 a;
    asm("{ .reg .u64 t; cvta.to.shared.u64 t, %1; cvt.u32.u64 %0, t; }" : "=r"(a) : "l"(p));
    return a;
}
__device__ __forceinline__ void cp16(u32 s, const void* g) {
    asm volatile("cp.async.cg.shared.global [%0], [%1], 16;" :: "r"(s), "l"(g) : "memory");
}
#define CP_COMMIT() asm volatile("cp.async.commit_group;" ::: "memory")
#define CP_WAIT(n)  asm volatile("cp.async.wait_group %0;" :: "n"(n) : "memory")

__device__ __forceinline__ void ldsm4(u32* r, u32 a) {
    asm volatile("ldmatrix.sync.aligned.m8n8.x4.shared.b16 {%0,%1,%2,%3}, [%4];"
                 : "=r"(r[0]), "=r"(r[1]), "=r"(r[2]), "=r"(r[3]) : "r"(a));
}
__device__ __forceinline__ void ldsm2(u32* r, u32 a) {
    asm volatile("ldmatrix.sync.aligned.m8n8.x2.shared.b16 {%0,%1}, [%2];"
                 : "=r"(r[0]), "=r"(r[1]) : "r"(a));
}
__device__ __forceinline__ void mma16816(float* d, const u32* a, const u32* b) {
    asm volatile("mma.sync.aligned.m16n8k16.row.col.f32.bf16.bf16.f32 "
                 "{%0,%1,%2,%3}, {%4,%5,%6,%7}, {%8,%9}, {%0,%1,%2,%3};"
                 : "+f"(d[0]), "+f"(d[1]), "+f"(d[2]), "+f"(d[3])
                 : "r"(a[0]), "r"(a[1]), "r"(a[2]), "r"(a[3]), "r"(b[0]), "r"(b[1]));
}

// ---------------------------------------------------------------
// Preprocessing
// ---------------------------------------------------------------
__device__ __forceinline__ void split2(float v, __nv_bfloat16& h, __nv_bfloat16& l) {
    h = __float2bfloat16_rn(v);
    l = __float2bfloat16_rn(v - __bfloat162float(h));
}

__global__ void xsplit_kernel(const float* __restrict__ x,
                              __nv_bfloat16* __restrict__ xh,
                              __nv_bfloat16* __restrict__ xl, long long n)
{
    long long j = ((long long)blockIdx.x * blockDim.x + threadIdx.x) * 4;
    if (j >= n) return;
    float4 v = *(const float4*)&x[j];
    __nv_bfloat16 hb[4], lb[4];
    split2(v.x, hb[0], lb[0]); split2(v.y, hb[1], lb[1]);
    split2(v.z, hb[2], lb[2]); split2(v.w, hb[3], lb[3]);
    *(uint2*)&xh[j] = *(const uint2*)hb;
    *(uint2*)&xl[j] = *(const uint2*)lb;
}

// Integer-exact Catmull-Rom grid: i = floor(j*(nc-1)/(n-1)), f = frac.
// One u64 div per thread (8 elems), then incremental carry. No fp64.
__global__ void spline_split_kernel(const float* __restrict__ cp,
                                    __nv_bfloat16* __restrict__ wh,
                                    __nv_bfloat16* __restrict__ wl,
                                    int n_ctrl, long long n)
{
    const long long j0 = ((long long)blockIdx.x * blockDim.x + threadIdx.x) * 8;
    if (j0 >= n) return;
    const u64 nm1 = (u64)(n - 1);
    const u64 ncm1 = (u64)(n_ctrl - 1);
    u64 num = (u64)j0 * ncm1;
    u64 i = num / nm1;
    u64 rem = num - i * nm1;
    const float inv = 1.0f / (float)nm1;

    __align__(16) __nv_bfloat16 hb[8];
    __align__(16) __nv_bfloat16 lb[8];

#pragma unroll
    for (int e = 0; e < 8; e++) {
        long long ii;
        float f;
        if (i >= ncm1) { ii = (long long)ncm1 - 1; f = 1.0f; }
        else           { ii = (long long)i;        f = (float)rem * inv; }

        const int i1 = (int)ii;
        const int i0 = i1 > 0 ? i1 - 1 : 0;
        const int i2 = i1 + 1;
        const int i3 = (u64)(i1 + 2) > ncm1 ? (int)ncm1 : i1 + 2;

        const float p0 = cp[i0], p1 = cp[i1], p2 = cp[i2], p3 = cp[i3];
        const float f2 = f * f;
        const float f3 = f2 * f;
        const float val = 0.5f * (2.0f * p1
                   + (p2 - p0) * f
                   + (2.0f * p0 - 5.0f * p1 + 4.0f * p2 - p3) * f2
                   + (3.0f * p1 - p0 - 3.0f * p2 + p3) * f3);
        split2(val, hb[e], lb[e]);

        rem += ncm1;
        if (rem >= nm1) { rem -= nm1; i++; }
    }
    *(uint4*)&wh[j0] = *(const uint4*)hb;
    *(uint4*)&wl[j0] = *(const uint4*)lb;
}

// ---------------------------------------------------------------
// Tensor-core NT GEMM via mma.sync (bf16, fp32 acc), split-bf16
// 3-pass: acc += Ah*Bh + Ah*Bl + Al*Bh
// Block 128x128(xNB), BK=32, 8 warps (2M x 4N), warp tile 64x32.
// NB=2 + EPI=1: fused gate+up, SwiGLU in registers -> bf16 hi/lo out.
// NB=1 + EPI=0: plain GEMM -> fp32 out.
// smem rows padded to 80B (conflict-free for STS.128 and ldmatrix).
// ---------------------------------------------------------------
#define ROWB   80
#define TILEB  (128 * ROWB)            // 10240 B per operand tile

template <int NB, int EPI, int NS>
__global__ void __launch_bounds__(256, 1)
gemm_mma(const __nv_bfloat16* __restrict__ Ah_,
         const __nv_bfloat16* __restrict__ Al_,
         const __nv_bfloat16* __restrict__ B0h_,
         const __nv_bfloat16* __restrict__ B0l_,
         const __nv_bfloat16* __restrict__ B1h_,
         const __nv_bfloat16* __restrict__ B1l_,
         float* __restrict__ Cf,
         __nv_bfloat16* __restrict__ Oh,
         __nv_bfloat16* __restrict__ Ol,
         int N, int K)
{
    constexpr u32 STAGEB = (u32)((2 + 2 * NB) * TILEB);
    extern __shared__ __align__(128) char sm[];
    const u32 sb = smem_u32(sm);
    const int tid  = threadIdx.x;
    const int lane = tid & 31;
    const int wid  = tid >> 5;
    const int wm   = wid & 1;
    const int wn   = wid >> 1;
    const int bm   = blockIdx.y * 128;
    const int bn   = blockIdx.x * 128;
    const int NC   = K >> 5;

    float acc[NB][4][4][4];
#pragma unroll
    for (int nb = 0; nb < NB; nb++)
#pragma unroll
        for (int mi = 0; mi < 4; mi++)
#pragma unroll
            for (int ni = 0; ni < 4; ni++)
#pragma unroll
                for (int q = 0; q < 4; q++) acc[nb][mi][ni][q] = 0.0f;

    const int r0 = tid >> 2;
    const int r1 = r0 + 64;
    const int c0 = (tid & 3) * 8;

    auto issue_stage = [&](int stg) {
        const u32 base = sb + (u32)(stg % NS) * STAGEB;
        const int k0 = stg * 32;
#pragma unroll
        for (int half = 0; half < 2; half++) {
            const int r = half ? r1 : r0;
            const u32 so = base + (u32)r * ROWB + (u32)(c0 >> 3) * 16;
            const size_t ga = (size_t)(bm + r) * K + k0 + c0;
            const size_t gb = (size_t)(bn + r) * K + k0 + c0;
            cp16(so + 0 * TILEB, Ah_ + ga);
            cp16(so + 1 * TILEB, Al_ + ga);
            cp16(so + 2 * TILEB, B0h_ + gb);
            cp16(so + 3 * TILEB, B0l_ + gb);
            if (NB == 2) {
                cp16(so + 4 * TILEB, B1h_ + gb);
                cp16(so + 5 * TILEB, B1l_ + gb);
            }
        }
    };

#pragma unroll
    for (int s = 0; s < NS - 1; s++) {
        if (s < NC) issue_stage(s);
        CP_COMMIT();
    }

    const int alr = lane & 15;
    const int alc = (lane >> 4) << 3;
    const int blr = lane & 7;
    const int blc = ((lane >> 3) & 1) << 3;

    for (int c = 0; c < NC; c++) {
        const int pf = c + NS - 1;
        if (pf < NC) issue_stage(pf);
        CP_COMMIT();
        CP_WAIT(NS - 1);
        __syncthreads();

        const u32 stb = sb + (u32)(c % NS) * STAGEB;

#pragma unroll
        for (int ks = 0; ks < 2; ks++) {
            u32 ah[4][4], al[4][4];
#pragma unroll
            for (int mi = 0; mi < 4; mi++) {
                const u32 ra = stb + (u32)(wm * 64 + mi * 16 + alr) * ROWB
                             + (u32)(ks * 16 + alc) * 2;
                ldsm4(ah[mi], ra);
                ldsm4(al[mi], ra + TILEB);
            }
#pragma unroll
            for (int nb = 0; nb < NB; nb++) {
                u32 bh[4][2], bl[4][2];
#pragma unroll
                for (int ni = 0; ni < 4; ni++) {
                    const u32 rb = stb + (u32)(2 + 2 * nb) * TILEB
                                 + (u32)(wn * 32 + ni * 8 + blr) * ROWB
                                 + (u32)(ks * 16 + blc) * 2;
                    ldsm2(bh[ni], rb);
                    ldsm2(bl[ni], rb + TILEB);
                }
#pragma unroll
                for (int mi = 0; mi < 4; mi++)
#pragma unroll
                    for (int ni = 0; ni < 4; ni++) {
                        mma16816(acc[nb][mi][ni], ah[mi], bh[ni]);
                        mma16816(acc[nb][mi][ni], ah[mi], bl[ni]);
                        mma16816(acc[nb][mi][ni], al[mi], bh[ni]);
                    }
            }
        }
        __syncthreads();
    }

    // ---------------- epilogue ----------------
    const int er = lane >> 2;
    const int ec = (lane & 3) * 2;
#pragma unroll
    for (int mi = 0; mi < 4; mi++) {
#pragma unroll
        for (int ni = 0; ni < 4; ni++) {
            const int row = bm + wm * 64 + mi * 16 + er;
            const int col = bn + wn * 32 + ni * 8 + ec;
            if (EPI == 0) {
                const float* d = acc[0][mi][ni];
                *(float2*)&Cf[(size_t)row * N + col] = make_float2(d[0], d[1]);
                *(float2*)&Cf[(size_t)(row + 8) * N + col] = make_float2(d[2], d[3]);
            } else {
                const float* dg = acc[0][mi][ni];
                const float* du = acc[1][mi][ni];
#pragma unroll
                for (int h = 0; h < 2; h++) {
                    const size_t off = (size_t)(row + h * 8) * N + col;
                    float g0 = dg[h * 2 + 0], g1 = dg[h * 2 + 1];
                    float v0 = (g0 / (1.0f + expf(-g0))) * du[h * 2 + 0];
                    float v1 = (g1 / (1.0f + expf(-g1))) * du[h * 2 + 1];
                    __nv_bfloat16 h0, l0, h1, l1;
                    split2(v0, h0, l0);
                    split2(v1, h1, l1);
                    u32 ph = (u32)__bfloat16_as_ushort(h0) |
                             ((u32)__bfloat16_as_ushort(h1) << 16);
                    u32 pl = (u32)__bfloat16_as_ushort(l0) |
                             ((u32)__bfloat16_as_ushort(l1) << 16);
                    *(u32*)&Oh[off] = ph;
                    *(u32*)&Ol[off] = pl;
                }
            }
        }
    }
}

// ---------------------------------------------------------------
// Launch
// ---------------------------------------------------------------
extern "C" void kernel_launch(void* const* d_in, const int* in_sizes, int n_in,
                              void* d_out, int out_size)
{
    (void)n_in; (void)out_size;
    const float* x   = (const float*)d_in[0];
    const float* gcp = (const float*)d_in[1];
    const float* ucp = (const float*)d_in[2];
    const float* dcp = (const float*)d_in[3];
    float* out = (float*)d_out;

    const int M = in_sizes[0] / HID;   // 8192

    void *xh, *xl, *gwh, *gwl, *uwh, *uwl, *dwh, *dwl, *ith, *itl;
    cudaGetSymbolAddress(&xh, g_xh);   cudaGetSymbolAddress(&xl, g_xl);
    cudaGetSymbolAddress(&gwh, g_gwh); cudaGetSymbolAddress(&gwl, g_gwl);
    cudaGetSymbolAddress(&uwh, g_uwh); cudaGetSymbolAddress(&uwl, g_uwl);
    cudaGetSymbolAddress(&dwh, g_dwh); cudaGetSymbolAddress(&dwl, g_dwl);
    cudaGetSymbolAddress(&ith, g_ith); cudaGetSymbolAddress(&itl, g_itl);

    constexpr int SMEM_F = 3 * 6 * TILEB;   // NS=3, 6 tiles: 184320
    constexpr int SMEM_D = 4 * 4 * TILEB;   // NS=4, 4 tiles: 163840
    cudaFuncSetAttribute(gemm_mma<2, 1, 3>,
                         cudaFuncAttributeMaxDynamicSharedMemorySize, SMEM_F);
    cudaFuncSetAttribute(gemm_mma<1, 0, 4>,
                         cudaFuncAttributeMaxDynamicSharedMemorySize, SMEM_D);

    long long nX = (long long)M * HID;
    xsplit_kernel<<<(int)((nX / 4 + 255) / 256), 256>>>(x, (__nv_bfloat16*)xh,
                                                        (__nv_bfloat16*)xl, nX);
    long long nw = (long long)NW;
    int sbk = (int)((nw / 8 + 255) / 256);
    spline_split_kernel<<<sbk, 256>>>(gcp, (__nv_bfloat16*)gwh, (__nv_bfloat16*)gwl,
                                      in_sizes[1], nw);
    spline_split_kernel<<<sbk, 256>>>(ucp, (__nv_bfloat16*)uwh, (__nv_bfloat16*)uwl,
                                      in_sizes[2], nw);
    spline_split_kernel<<<sbk, 256>>>(dcp, (__nv_bfloat16*)dwh, (__nv_bfloat16*)dwl,
                                      in_sizes[3], nw);

    // fused: it = silu(X Gw^T) * (X Uw^T)  -> bf16 hi/lo
    dim3 g1(ITR / 128, M / 128);
    gemm_mma<2, 1, 3><<<g1, 256, SMEM_F>>>(
        (const __nv_bfloat16*)xh, (const __nv_bfloat16*)xl,
        (const __nv_bfloat16*)gwh, (const __nv_bfloat16*)gwl,
        (const __nv_bfloat16*)uwh, (const __nv_bfloat16*)uwl,
        nullptr, (__nv_bfloat16*)ith, (__nv_bfloat16*)itl, ITR, HID);

    // down: out = it Dw^T  (fp32)
    dim3 g2(HID / 128, M / 128);
    gemm_mma<1, 0, 4><<<g2, 256, SMEM_D>>>(
        (const __nv_bfloat16*)ith, (const __nv_bfloat16*)itl,
        (const __nv_bfloat16*)dwh, (const __nv_bfloat16*)dwl,
        nullptr, nullptr,
        out, nullptr, nullptr, HID, ITR);
}

// round 11
// speedup vs baseline: 3.0995x; 1.0268x over previous
#include <cuda_runtime.h>
#include <cuda_bf16.h>
#include <stdint.h>
#include <math.h>

#define HID   2048
#define ITR   8192
#define MTOK  8192
#define NW ((size_t)ITR * (size_t)HID)

typedef uint32_t u32;
typedef unsigned long long u64;

// ---------------------------------------------------------------
// Static device scratch (no cudaMalloc allowed)
// ---------------------------------------------------------------
__device__ __align__(256) __nv_bfloat16 g_xh[(size_t)MTOK * HID];
__device__ __align__(256) __nv_bfloat16 g_xl[(size_t)MTOK * HID];
__device__ __align__(256) __nv_bfloat16 g_gwh[NW];
__device__ __align__(256) __nv_bfloat16 g_gwl[NW];
__device__ __align__(256) __nv_bfloat16 g_uwh[NW];
__device__ __align__(256) __nv_bfloat16 g_uwl[NW];
__device__ __align__(256) __nv_bfloat16 g_dwh[NW];
__device__ __align__(256) __nv_bfloat16 g_dwl[NW];
__device__ __align__(256) __nv_bfloat16 g_ith[(size_t)MTOK * ITR];
__device__ __align__(256) __nv_bfloat16 g_itl[(size_t)MTOK * ITR];

// ---------------------------------------------------------------
// PTX helpers (baseline sm_80/90 PTX only — nothing 'a'-gated)
// ---------------------------------------------------------------
__device__ __forceinline__ u32 smem_u32(const void* p) {
    u32 a;
    asm("{ .reg .u64 t; cvta.to.shared.u64 t, %1; cvt.u32.u64 %0, t; }" : "=r"(a) : "l"(p));
    return a;
}
__device__ __forceinline__ void cp16(u32 s, const void* g) {
    asm volatile("cp.async.cg.shared.global [%0], [%1], 16;" :: "r"(s), "l"(g) : "memory");
}
#define CP_COMMIT() asm volatile("cp.async.commit_group;" ::: "memory")
#define CP_WAIT(n)  asm volatile("cp.async.wait_group %0;" :: "n"(n) : "memory")

__device__ __forceinline__ void ldsm4(u32* r, u32 a) {
    asm volatile("ldmatrix.sync.aligned.m8n8.x4.shared.b16 {%0,%1,%2,%3}, [%4];"
                 : "=r"(r[0]), "=r"(r[1]), "=r"(r[2]), "=r"(r[3]) : "r"(a));
}
__device__ __forceinline__ void mma16816(float* d, const u32* a, const u32* b) {
    asm volatile("mma.sync.aligned.m16n8k16.row.col.f32.bf16.bf16.f32 "
                 "{%0,%1,%2,%3}, {%4,%5,%6,%7}, {%8,%9}, {%0,%1,%2,%3};"
                 : "+f"(d[0]), "+f"(d[1]), "+f"(d[2]), "+f"(d[3])
                 : "r"(a[0]), "r"(a[1]), "r"(a[2]), "r"(a[3]), "r"(b[0]), "r"(b[1]));
}

// ---------------------------------------------------------------
// Preprocessing
// ---------------------------------------------------------------
__device__ __forceinline__ void split2(float v, __nv_bfloat16& h, __nv_bfloat16& l) {
    h = __float2bfloat16_rn(v);
    l = __float2bfloat16_rn(v - __bfloat162float(h));
}

__global__ void xsplit_kernel(const float* __restrict__ x,
                              __nv_bfloat16* __restrict__ xh,
                              __nv_bfloat16* __restrict__ xl, long long n)
{
    long long j = ((long long)blockIdx.x * blockDim.x + threadIdx.x) * 4;
    if (j >= n) return;
    float4 v = *(const float4*)&x[j];
    __nv_bfloat16 hb[4], lb[4];
    split2(v.x, hb[0], lb[0]); split2(v.y, hb[1], lb[1]);
    split2(v.z, hb[2], lb[2]); split2(v.w, hb[3], lb[3]);
    *(uint2*)&xh[j] = *(const uint2*)hb;
    *(uint2*)&xl[j] = *(const uint2*)lb;
}

// Integer-exact Catmull-Rom: i = floor(j*(nc-1)/(n-1)), f = rem/(n-1).
// One u64 div per thread (8 elems), u32 incremental carry. No fp64.
struct SplineJob {
    const float* cp;
    __nv_bfloat16* wh;
    __nv_bfloat16* wl;
    int n_ctrl;
};

__global__ void spline3_kernel(SplineJob ja, SplineJob jb_, SplineJob jc, long long n)
{
    const SplineJob J = (blockIdx.y == 0) ? ja : (blockIdx.y == 1) ? jb_ : jc;
    const float* __restrict__ cp = J.cp;
    const long long j0 = ((long long)blockIdx.x * blockDim.x + threadIdx.x) * 8;
    if (j0 >= n) return;

    const u32 nm1 = (u32)(n - 1);
    const u32 ncm1 = (u32)(J.n_ctrl - 1);
    const u64 num = (u64)j0 * ncm1;
    u32 i = (u32)(num / nm1);
    u32 rem = (u32)(num - (u64)i * nm1);
    const float inv = 1.0f / (float)nm1;

    __align__(16) __nv_bfloat16 hb[8];
    __align__(16) __nv_bfloat16 lb[8];

#pragma unroll
    for (int e = 0; e < 8; e++) {
        int i1;
        float f;
        if (i >= ncm1) { i1 = (int)ncm1 - 1; f = 1.0f; }
        else           { i1 = (int)i;        f = (float)rem * inv; }

        const int i0 = i1 > 0 ? i1 - 1 : 0;
        const int i2 = i1 + 1;
        const int i3 = (u32)(i1 + 2) > ncm1 ? (int)ncm1 : i1 + 2;

        const float p0 = cp[i0], p1 = cp[i1], p2 = cp[i2], p3 = cp[i3];
        const float f2 = f * f;
        const float f3 = f2 * f;
        const float val = 0.5f * (2.0f * p1
                   + (p2 - p0) * f
                   + (2.0f * p0 - 5.0f * p1 + 4.0f * p2 - p3) * f2
                   + (3.0f * p1 - p0 - 3.0f * p2 + p3) * f3);
        split2(val, hb[e], lb[e]);

        rem += ncm1;
        if (rem >= nm1) { rem -= nm1; i++; }
    }
    *(uint4*)&J.wh[j0] = *(const uint4*)hb;
    *(uint4*)&J.wl[j0] = *(const uint4*)lb;
}

// ---------------------------------------------------------------
// Tensor-core NT GEMM via mma.sync (bf16, fp32 acc), split-bf16
// 3-pass: acc += Ah*Bh + Ah*Bl + Al*Bh
// Block 128x128(xNB), BK=32, 8 warps (2M x 4N), warp tile 64x32.
// Single __syncthreads per chunk; early prefetch-issue after barrier.
// 1D grid with 8-row raster swizzle for L2 reuse.
// NB=2 + EPI=1: fused gate+up, SwiGLU in registers -> bf16 hi/lo out.
// NB=1 + EPI=0: plain GEMM -> fp32 out.
// ---------------------------------------------------------------
#define ROWB   80
#define TILEB  (128 * ROWB)            // 10240 B per operand tile
#define GRP    8

template <int NB, int EPI, int NS>
__global__ void __launch_bounds__(256, 1)
gemm_mma(const __nv_bfloat16* __restrict__ Ah_,
         const __nv_bfloat16* __restrict__ Al_,
         const __nv_bfloat16* __restrict__ B0h_,
         const __nv_bfloat16* __restrict__ B0l_,
         const __nv_bfloat16* __restrict__ B1h_,
         const __nv_bfloat16* __restrict__ B1l_,
         float* __restrict__ Cf,
         __nv_bfloat16* __restrict__ Oh,
         __nv_bfloat16* __restrict__ Ol,
         int N, int K)
{
    constexpr u32 STAGEB = (u32)((2 + 2 * NB) * TILEB);
    extern __shared__ __align__(128) char sm[];
    const u32 sb = smem_u32(sm);
    const int tid  = threadIdx.x;
    const int lane = tid & 31;
    const int wid  = tid >> 5;
    const int wm   = wid & 1;
    const int wn   = wid >> 1;

    // raster swizzle: 8 bm-rows per group, bn sweeps within group
    const int tiles_n = N >> 7;
    const int per = GRP * tiles_n;
    const int grp = blockIdx.x / per;
    const int wit = blockIdx.x % per;
    const int bm = (grp * GRP + (wit % GRP)) * 128;
    const int bn = (wit / GRP) * 128;

    const int NC = K >> 5;

    float acc[NB][4][4][4];
#pragma unroll
    for (int nb = 0; nb < NB; nb++)
#pragma unroll
        for (int mi = 0; mi < 4; mi++)
#pragma unroll
            for (int ni = 0; ni < 4; ni++)
#pragma unroll
                for (int q = 0; q < 4; q++) acc[nb][mi][ni][q] = 0.0f;

    const int r0 = tid >> 2;
    const int r1 = r0 + 64;
    const int c0 = (tid & 3) * 8;

    auto issue_stage = [&](int stg) {
        const u32 base = sb + (u32)(stg % NS) * STAGEB;
        const int k0 = stg * 32;
#pragma unroll
        for (int half = 0; half < 2; half++) {
            const int r = half ? r1 : r0;
            const u32 so = base + (u32)r * ROWB + (u32)(c0 >> 3) * 16;
            const size_t ga = (size_t)(bm + r) * K + k0 + c0;
            const size_t gb = (size_t)(bn + r) * K + k0 + c0;
            cp16(so + 0 * TILEB, Ah_ + ga);
            cp16(so + 1 * TILEB, Al_ + ga);
            cp16(so + 2 * TILEB, B0h_ + gb);
            cp16(so + 3 * TILEB, B0l_ + gb);
            if (NB == 2) {
                cp16(so + 4 * TILEB, B1h_ + gb);
                cp16(so + 5 * TILEB, B1l_ + gb);
            }
        }
    };

#pragma unroll
    for (int s = 0; s < NS - 1; s++) {
        if (s < NC) issue_stage(s);
        CP_COMMIT();
    }

    const int alr = lane & 15;
    const int alc = (lane >> 4) << 3;
    // B pair-ldsm4: lanes 0-7: ni rows (k-lo), 8-15: ni rows (k-hi),
    //               16-23: ni+1 rows (k-lo), 24-31: ni+1 rows (k-hi)
    const int blr4 = ((lane >> 4) & 1) * 8 + (lane & 7);
    const int blc4 = ((lane >> 3) & 1) * 8;

    for (int c = 0; c < NC; c++) {
        CP_WAIT(NS - 2);
        __syncthreads();

        const int pf = c + NS - 1;
        if (pf < NC) issue_stage(pf);
        CP_COMMIT();

        const u32 stb = sb + (u32)(c % NS) * STAGEB;

#pragma unroll
        for (int ks = 0; ks < 2; ks++) {
            u32 ah[4][4], al[4][4];
#pragma unroll
            for (int mi = 0; mi < 4; mi++) {
                const u32 ra = stb + (u32)(wm * 64 + mi * 16 + alr) * ROWB
                             + (u32)(ks * 16 + alc) * 2;
                ldsm4(ah[mi], ra);
                ldsm4(al[mi], ra + TILEB);
            }
#pragma unroll
            for (int nb = 0; nb < NB; nb++) {
                u32 bh[4][2], bl[4][2];
#pragma unroll
                for (int p = 0; p < 2; p++) {
                    const u32 rb = stb + (u32)(2 + 2 * nb) * TILEB
                                 + (u32)(wn * 32 + p * 16 + blr4) * ROWB
                                 + (u32)(ks * 16 + blc4) * 2;
                    u32 t[4];
                    ldsm4(t, rb);
                    bh[p * 2 + 0][0] = t[0]; bh[p * 2 + 0][1] = t[1];
                    bh[p * 2 + 1][0] = t[2]; bh[p * 2 + 1][1] = t[3];
                    ldsm4(t, rb + TILEB);
                    bl[p * 2 + 0][0] = t[0]; bl[p * 2 + 0][1] = t[1];
                    bl[p * 2 + 1][0] = t[2]; bl[p * 2 + 1][1] = t[3];
                }
#pragma unroll
                for (int mi = 0; mi < 4; mi++)
#pragma unroll
                    for (int ni = 0; ni < 4; ni++) {
                        mma16816(acc[nb][mi][ni], ah[mi], bh[ni]);
                        mma16816(acc[nb][mi][ni], ah[mi], bl[ni]);
                        mma16816(acc[nb][mi][ni], al[mi], bh[ni]);
                    }
            }
        }
    }

    // ---------------- epilogue ----------------
    const int er = lane >> 2;
    const int ec = (lane & 3) * 2;
#pragma unroll
    for (int mi = 0; mi < 4; mi++) {
#pragma unroll
        for (int ni = 0; ni < 4; ni++) {
            const int row = bm + wm * 64 + mi * 16 + er;
            const int col = bn + wn * 32 + ni * 8 + ec;
            if (EPI == 0) {
                const float* d = acc[0][mi][ni];
                *(float2*)&Cf[(size_t)row * N + col] = make_float2(d[0], d[1]);
                *(float2*)&Cf[(size_t)(row + 8) * N + col] = make_float2(d[2], d[3]);
            } else {
                const float* dg = acc[0][mi][ni];
                const float* du = acc[1][mi][ni];
#pragma unroll
                for (int h = 0; h < 2; h++) {
                    const size_t off = (size_t)(row + h * 8) * N + col;
                    float g0 = dg[h * 2 + 0], g1 = dg[h * 2 + 1];
                    float v0 = (g0 / (1.0f + expf(-g0))) * du[h * 2 + 0];
                    float v1 = (g1 / (1.0f + expf(-g1))) * du[h * 2 + 1];
                    __nv_bfloat16 h0, l0, h1, l1;
                    split2(v0, h0, l0);
                    split2(v1, h1, l1);
                    u32 ph = (u32)__bfloat16_as_ushort(h0) |
                             ((u32)__bfloat16_as_ushort(h1) << 16);
                    u32 pl = (u32)__bfloat16_as_ushort(l0) |
                             ((u32)__bfloat16_as_ushort(l1) << 16);
                    *(u32*)&Oh[off] = ph;
                    *(u32*)&Ol[off] = pl;
                }
            }
        }
    }
}

// ---------------------------------------------------------------
// Launch
// ---------------------------------------------------------------
extern "C" void kernel_launch(void* const* d_in, const int* in_sizes, int n_in,
                              void* d_out, int out_size)
{
    (void)n_in; (void)out_size;
    const float* x   = (const float*)d_in[0];
    const float* gcp = (const float*)d_in[1];
    const float* ucp = (const float*)d_in[2];
    const float* dcp = (const float*)d_in[3];
    float* out = (float*)d_out;

    const int M = in_sizes[0] / HID;   // 8192

    void *xh, *xl, *gwh, *gwl, *uwh, *uwl, *dwh, *dwl, *ith, *itl;
    cudaGetSymbolAddress(&xh, g_xh);   cudaGetSymbolAddress(&xl, g_xl);
    cudaGetSymbolAddress(&gwh, g_gwh); cudaGetSymbolAddress(&gwl, g_gwl);
    cudaGetSymbolAddress(&uwh, g_uwh); cudaGetSymbolAddress(&uwl, g_uwl);
    cudaGetSymbolAddress(&dwh, g_dwh); cudaGetSymbolAddress(&dwl, g_dwl);
    cudaGetSymbolAddress(&ith, g_ith); cudaGetSymbolAddress(&itl, g_itl);

    constexpr int SMEM_F = 3 * 6 * TILEB;   // NS=3, 6 tiles: 184320
    constexpr int SMEM_D = 5 * 4 * TILEB;   // NS=5, 4 tiles: 204800
    cudaFuncSetAttribute(gemm_mma<2, 1, 3>,
                         cudaFuncAttributeMaxDynamicSharedMemorySize, SMEM_F);
    cudaFuncSetAttribute(gemm_mma<1, 0, 5>,
                         cudaFuncAttributeMaxDynamicSharedMemorySize, SMEM_D);

    long long nX = (long long)M * HID;
    xsplit_kernel<<<(int)((nX / 4 + 255) / 256), 256>>>(x, (__nv_bfloat16*)xh,
                                                        (__nv_bfloat16*)xl, nX);
    long long nw = (long long)NW;
    SplineJob jg = { gcp, (__nv_bfloat16*)gwh, (__nv_bfloat16*)gwl, in_sizes[1] };
    SplineJob ju = { ucp, (__nv_bfloat16*)uwh, (__nv_bfloat16*)uwl, in_sizes[2] };
    SplineJob jd = { dcp, (__nv_bfloat16*)dwh, (__nv_bfloat16*)dwl, in_sizes[3] };
    dim3 sg((u32)((nw / 8 + 255) / 256), 3);
    spline3_kernel<<<sg, 256>>>(jg, ju, jd, nw);

    // fused: it = silu(X Gw^T) * (X Uw^T)  -> bf16 hi/lo
    const int g1 = (M / 128) * (ITR / 128);
    gemm_mma<2, 1, 3><<<g1, 256, SMEM_F>>>(
        (const __nv_bfloat16*)xh, (const __nv_bfloat16*)xl,
        (const __nv_bfloat16*)gwh, (const __nv_bfloat16*)gwl,
        (const __nv_bfloat16*)uwh, (const __nv_bfloat16*)uwl,
        nullptr, (__nv_bfloat16*)ith, (__nv_bfloat16*)itl, ITR, HID);

    // down: out = it Dw^T  (fp32)
    const int g2 = (M / 128) * (HID / 128);
    gemm_mma<1, 0, 5><<<g2, 256, SMEM_D>>>(
        (const __nv_bfloat16*)ith, (const __nv_bfloat16*)itl,
        (const __nv_bfloat16*)dwh, (const __nv_bfloat16*)dwl,
        nullptr, nullptr,
        out, nullptr, nullptr, HID, ITR);
}

// round 14
// speedup vs baseline: 3.6505x; 1.1778x over previous
#include <cuda_runtime.h>
#include <cuda_bf16.h>
#include <stdint.h>
#include <math.h>

#define HID   2048
#define ITR   8192
#define MTOK  8192
#define NW ((size_t)ITR * (size_t)HID)

typedef uint32_t u32;
typedef unsigned long long u64;

// ---------------------------------------------------------------
// Static device scratch (no cudaMalloc allowed)
// ---------------------------------------------------------------
__device__ __align__(256) __nv_bfloat16 g_xh[(size_t)MTOK * HID];
__device__ __align__(256) __nv_bfloat16 g_xl[(size_t)MTOK * HID];
__device__ __align__(256) __nv_bfloat16 g_gwh[NW];
__device__ __align__(256) __nv_bfloat16 g_gwl[NW];
__device__ __align__(256) __nv_bfloat16 g_uwh[NW];
__device__ __align__(256) __nv_bfloat16 g_uwl[NW];
__device__ __align__(256) __nv_bfloat16 g_dwh[NW];
__device__ __align__(256) __nv_bfloat16 g_dwl[NW];
__device__ __align__(256) __nv_bfloat16 g_ith[(size_t)MTOK * ITR];
__device__ __align__(256) __nv_bfloat16 g_itl[(size_t)MTOK * ITR];

// ---------------------------------------------------------------
// PTX helpers (baseline sm_80/90 PTX only — nothing 'a'-gated)
// ---------------------------------------------------------------
__device__ __forceinline__ u32 smem_u32(const void* p) {
    u32 a;
    asm("{ .reg .u64 t; cvta.to.shared.u64 t, %1; cvt.u32.u64 %0, t; }" : "=r"(a) : "l"(p));
    return a;
}
__device__ __forceinline__ void cp16(u32 s, const void* g) {
    asm volatile("cp.async.cg.shared.global [%0], [%1], 16;" :: "r"(s), "l"(g) : "memory");
}
#define CP_COMMIT() asm volatile("cp.async.commit_group;" ::: "memory")
#define CP_WAIT(n)  asm volatile("cp.async.wait_group %0;" :: "n"(n) : "memory")

__device__ __forceinline__ void ldsm4(u32* r, u32 a) {
    asm volatile("ldmatrix.sync.aligned.m8n8.x4.shared.b16 {%0,%1,%2,%3}, [%4];"
                 : "=r"(r[0]), "=r"(r[1]), "=r"(r[2]), "=r"(r[3]) : "r"(a));
}
__device__ __forceinline__ void mma16816(float* d, const u32* a, const u32* b) {
    asm volatile("mma.sync.aligned.m16n8k16.row.col.f32.bf16.bf16.f32 "
                 "{%0,%1,%2,%3}, {%4,%5,%6,%7}, {%8,%9}, {%0,%1,%2,%3};"
                 : "+f"(d[0]), "+f"(d[1]), "+f"(d[2]), "+f"(d[3])
                 : "r"(a[0]), "r"(a[1]), "r"(a[2]), "r"(a[3]), "r"(b[0]), "r"(b[1]));
}

// ---------------------------------------------------------------
// Preprocessing
// ---------------------------------------------------------------
__device__ __forceinline__ void split2(float v, __nv_bfloat16& h, __nv_bfloat16& l) {
    h = __float2bfloat16_rn(v);
    l = __float2bfloat16_rn(v - __bfloat162float(h));
}

__global__ void xsplit_kernel(const float* __restrict__ x,
                              __nv_bfloat16* __restrict__ xh,
                              __nv_bfloat16* __restrict__ xl, long long n)
{
    long long j = ((long long)blockIdx.x * blockDim.x + threadIdx.x) * 4;
    if (j >= n) return;
    float4 v = *(const float4*)&x[j];
    __nv_bfloat16 hb[4], lb[4];
    split2(v.x, hb[0], lb[0]); split2(v.y, hb[1], lb[1]);
    split2(v.z, hb[2], lb[2]); split2(v.w, hb[3], lb[3]);
    *(uint2*)&xh[j] = *(const uint2*)hb;
    *(uint2*)&xl[j] = *(const uint2*)lb;
}

// Integer-exact Catmull-Rom: i = floor(j*(nc-1)/(n-1)), f = rem/(n-1).
struct SplineJob {
    const float* cp;
    __nv_bfloat16* wh;
    __nv_bfloat16* wl;
    int n_ctrl;
};

__global__ void spline3_kernel(SplineJob ja, SplineJob jb_, SplineJob jc, long long n)
{
    const SplineJob J = (blockIdx.y == 0) ? ja : (blockIdx.y == 1) ? jb_ : jc;
    const float* __restrict__ cp = J.cp;
    const long long j0 = ((long long)blockIdx.x * blockDim.x + threadIdx.x) * 8;
    if (j0 >= n) return;

    const u32 nm1 = (u32)(n - 1);
    const u32 ncm1 = (u32)(J.n_ctrl - 1);
    const u64 num = (u64)j0 * ncm1;
    u32 i = (u32)(num / nm1);
    u32 rem = (u32)(num - (u64)i * nm1);
    const float inv = 1.0f / (float)nm1;

    __align__(16) __nv_bfloat16 hb[8];
    __align__(16) __nv_bfloat16 lb[8];

#pragma unroll
    for (int e = 0; e < 8; e++) {
        int i1;
        float f;
        if (i >= ncm1) { i1 = (int)ncm1 - 1; f = 1.0f; }
        else           { i1 = (int)i;        f = (float)rem * inv; }

        const int i0 = i1 > 0 ? i1 - 1 : 0;
        const int i2 = i1 + 1;
        const int i3 = (u32)(i1 + 2) > ncm1 ? (int)ncm1 : i1 + 2;

        const float p0 = cp[i0], p1 = cp[i1], p2 = cp[i2], p3 = cp[i3];
        const float f2 = f * f;
        const float f3 = f2 * f;
        const float val = 0.5f * (2.0f * p1
                   + (p2 - p0) * f
                   + (2.0f * p0 - 5.0f * p1 + 4.0f * p2 - p3) * f2
                   + (3.0f * p1 - p0 - 3.0f * p2 + p3) * f3);
        split2(val, hb[e], lb[e]);

        rem += ncm1;
        if (rem >= nm1) { rem -= nm1; i++; }
    }
    *(uint4*)&J.wh[j0] = *(const uint4*)hb;
    *(uint4*)&J.wl[j0] = *(const uint4*)lb;
}

// ---------------------------------------------------------------
// Tensor-core NT GEMM via mma.sync (bf16, fp32 acc), split-bf16
// 3-pass: acc += Ah*Bh + Ah*Bl + Al*Bh
// Block 128x128(xNB), BK=64, 8 warps (2M x 4N), warp tile 64x32.
// XOR-swizzled smem (128B rows, chunk c of row r at c^(r&7)):
// conflict-free for cp.async stores and ldmatrix reads, no padding.
// One __syncthreads per 64-deep K chunk (half the barriers of BK=32).
// NB=2 + EPI=1: fused gate+up, SwiGLU in registers -> bf16 hi/lo out.
// NB=1 + EPI=0: plain GEMM -> fp32 out.
// ---------------------------------------------------------------
#define TILEB  (128 * 128)             // 16384 B per operand tile (128 rows x 128B)
#define GRP    8

template <int NB, int EPI, int NS>
__global__ void __launch_bounds__(256, 1)
gemm_mma(const __nv_bfloat16* __restrict__ Ah_,
         const __nv_bfloat16* __restrict__ Al_,
         const __nv_bfloat16* __restrict__ B0h_,
         const __nv_bfloat16* __restrict__ B0l_,
         const __nv_bfloat16* __restrict__ B1h_,
         const __nv_bfloat16* __restrict__ B1l_,
         float* __restrict__ Cf,
         __nv_bfloat16* __restrict__ Oh,
         __nv_bfloat16* __restrict__ Ol,
         int N, int K)
{
    constexpr u32 STAGEB = (u32)((2 + 2 * NB) * TILEB);
    extern __shared__ __align__(128) char sm[];
    const u32 sb = smem_u32(sm);
    const int tid  = threadIdx.x;
    const int lane = tid & 31;
    const int wid  = tid >> 5;
    const int wm   = wid & 1;
    const int wn   = wid >> 1;

    // raster swizzle: 8 bm-rows per group, bn sweeps within group
    const int tiles_n = N >> 7;
    const int per = GRP * tiles_n;
    const int grp = blockIdx.x / per;
    const int wit = blockIdx.x % per;
    const int bm = (grp * GRP + (wit % GRP)) * 128;
    const int bn = (wit / GRP) * 128;

    const int NC = K >> 6;

    float acc[NB][4][4][4];
#pragma unroll
    for (int nb = 0; nb < NB; nb++)
#pragma unroll
        for (int mi = 0; mi < 4; mi++)
#pragma unroll
            for (int ni = 0; ni < 4; ni++)
#pragma unroll
                for (int q = 0; q < 4; q++) acc[nb][mi][ni][q] = 0.0f;

    // cp.async coords: rows tid>>2 and +64; chunks (tid&3)*2 and +1
    const int r0 = tid >> 2;
    const int cb0 = (tid & 3) * 2;

    auto issue_stage = [&](int stg) {
        const u32 base = sb + (u32)(stg % NS) * STAGEB;
        const int k0 = stg * 64;
#pragma unroll
        for (int half = 0; half < 2; half++) {
            const int r = r0 + half * 64;
#pragma unroll
            for (int q = 0; q < 2; q++) {
                const int ch = cb0 + q;
                const u32 so = base + (u32)r * 128 + (u32)((ch ^ (r & 7)) << 4);
                const size_t ga = (size_t)(bm + r) * K + k0 + ch * 8;
                const size_t gb = (size_t)(bn + r) * K + k0 + ch * 8;
                cp16(so + 0 * TILEB, Ah_ + ga);
                cp16(so + 1 * TILEB, Al_ + ga);
                cp16(so + 2 * TILEB, B0h_ + gb);
                cp16(so + 3 * TILEB, B0l_ + gb);
                if (NB == 2) {
                    cp16(so + 4 * TILEB, B1h_ + gb);
                    cp16(so + 5 * TILEB, B1l_ + gb);
                }
            }
        }
    };

#pragma unroll
    for (int s = 0; s < NS - 1; s++) {
        if (s < NC) issue_stage(s);
        CP_COMMIT();
    }

    // ldmatrix coords
    const int alr = lane & 15;               // A row within 16
    const int ach = lane >> 4;               // A chunk half (0/1)
    const int blr4 = ((lane >> 4) & 1) * 8 + (lane & 7);  // B pair rows
    const int bch = (lane >> 3) & 1;         // B chunk half (0/1)

    for (int c = 0; c < NC; c++) {
        CP_WAIT(NS - 2);
        __syncthreads();

        const int pf = c + NS - 1;
        if (pf < NC) issue_stage(pf);
        CP_COMMIT();

        const u32 stb = sb + (u32)(c % NS) * STAGEB;

#pragma unroll
        for (int kk = 0; kk < 4; kk++) {
            u32 ah[4][4], al[4][4];
#pragma unroll
            for (int mi = 0; mi < 4; mi++) {
                const int row = wm * 64 + mi * 16 + alr;
                const int ch = kk * 2 + ach;
                const u32 ra = stb + (u32)row * 128 + (u32)((ch ^ (row & 7)) << 4);
                ldsm4(ah[mi], ra);
                ldsm4(al[mi], ra + TILEB);
            }
#pragma unroll
            for (int nb = 0; nb < NB; nb++) {
                u32 bh[4][2], bl[4][2];
#pragma unroll
                for (int p = 0; p < 2; p++) {
                    const int row = wn * 32 + p * 16 + blr4;
                    const int ch = kk * 2 + bch;
                    const u32 rb = stb + (u32)(2 + 2 * nb) * TILEB
                                 + (u32)row * 128 + (u32)((ch ^ (row & 7)) << 4);
                    u32 t[4];
                    ldsm4(t, rb);
                    bh[p * 2 + 0][0] = t[0]; bh[p * 2 + 0][1] = t[1];
                    bh[p * 2 + 1][0] = t[2]; bh[p * 2 + 1][1] = t[3];
                    ldsm4(t, rb + TILEB);
                    bl[p * 2 + 0][0] = t[0]; bl[p * 2 + 0][1] = t[1];
                    bl[p * 2 + 1][0] = t[2]; bl[p * 2 + 1][1] = t[3];
                }
#pragma unroll
                for (int mi = 0; mi < 4; mi++)
#pragma unroll
                    for (int ni = 0; ni < 4; ni++) {
                        mma16816(acc[nb][mi][ni], ah[mi], bh[ni]);
                        mma16816(acc[nb][mi][ni], ah[mi], bl[ni]);
                        mma16816(acc[nb][mi][ni], al[mi], bh[ni]);
                    }
            }
        }
    }

    // ---------------- epilogue ----------------
    const int er = lane >> 2;
    const int ec = (lane & 3) * 2;
#pragma unroll
    for (int mi = 0; mi < 4; mi++) {
#pragma unroll
        for (int ni = 0; ni < 4; ni++) {
            const int row = bm + wm * 64 + mi * 16 + er;
            const int col = bn + wn * 32 + ni * 8 + ec;
            if (EPI == 0) {
                const float* d = acc[0][mi][ni];
                *(float2*)&Cf[(size_t)row * N + col] = make_float2(d[0], d[1]);
                *(float2*)&Cf[(size_t)(row + 8) * N + col] = make_float2(d[2], d[3]);
            } else {
                const float* dg = acc[0][mi][ni];
                const float* du = acc[1][mi][ni];
#pragma unroll
                for (int h = 0; h < 2; h++) {
                    const size_t off = (size_t)(row + h * 8) * N + col;
                    float g0 = dg[h * 2 + 0], g1 = dg[h * 2 + 1];
                    float v0 = (g0 / (1.0f + expf(-g0))) * du[h * 2 + 0];
                    float v1 = (g1 / (1.0f + expf(-g1))) * du[h * 2 + 1];
                    __nv_bfloat16 h0, l0, h1, l1;
                    split2(v0, h0, l0);
                    split2(v1, h1, l1);
                    u32 ph = (u32)__bfloat16_as_ushort(h0) |
                             ((u32)__bfloat16_as_ushort(h1) << 16);
                    u32 pl = (u32)__bfloat16_as_ushort(l0) |
                             ((u32)__bfloat16_as_ushort(l1) << 16);
                    *(u32*)&Oh[off] = ph;
                    *(u32*)&Ol[off] = pl;
                }
            }
        }
    }
}

// ---------------------------------------------------------------
// Launch
// ---------------------------------------------------------------
extern "C" void kernel_launch(void* const* d_in, const int* in_sizes, int n_in,
                              void* d_out, int out_size)
{
    (void)n_in; (void)out_size;
    const float* x   = (const float*)d_in[0];
    const float* gcp = (const float*)d_in[1];
    const float* ucp = (const float*)d_in[2];
    const float* dcp = (const float*)d_in[3];
    float* out = (float*)d_out;

    const int M = in_sizes[0] / HID;   // 8192

    void *xh, *xl, *gwh, *gwl, *uwh, *uwl, *dwh, *dwl, *ith, *itl;
    cudaGetSymbolAddress(&xh, g_xh);   cudaGetSymbolAddress(&xl, g_xl);
    cudaGetSymbolAddress(&gwh, g_gwh); cudaGetSymbolAddress(&gwl, g_gwl);
    cudaGetSymbolAddress(&uwh, g_uwh); cudaGetSymbolAddress(&uwl, g_uwl);
    cudaGetSymbolAddress(&dwh, g_dwh); cudaGetSymbolAddress(&dwl, g_dwl);
    cudaGetSymbolAddress(&ith, g_ith); cudaGetSymbolAddress(&itl, g_itl);

    constexpr int SMEM_F = 2 * 6 * TILEB;   // NS=2, 6 tiles: 196608
    constexpr int SMEM_D = 3 * 4 * TILEB;   // NS=3, 4 tiles: 196608
    cudaFuncSetAttribute(gemm_mma<2, 1, 2>,
                         cudaFuncAttributeMaxDynamicSharedMemorySize, SMEM_F);
    cudaFuncSetAttribute(gemm_mma<1, 0, 3>,
                         cudaFuncAttributeMaxDynamicSharedMemorySize, SMEM_D);

    long long nX = (long long)M * HID;
    xsplit_kernel<<<(int)((nX / 4 + 255) / 256), 256>>>(x, (__nv_bfloat16*)xh,
                                                        (__nv_bfloat16*)xl, nX);
    long long nw = (long long)NW;
    SplineJob jg = { gcp, (__nv_bfloat16*)gwh, (__nv_bfloat16*)gwl, in_sizes[1] };
    SplineJob ju = { ucp, (__nv_bfloat16*)uwh, (__nv_bfloat16*)uwl, in_sizes[2] };
    SplineJob jd = { dcp, (__nv_bfloat16*)dwh, (__nv_bfloat16*)dwl, in_sizes[3] };
    dim3 sg((u32)((nw / 8 + 255) / 256), 3);
    spline3_kernel<<<sg, 256>>>(jg, ju, jd, nw);

    // fused: it = silu(X Gw^T) * (X Uw^T)  -> bf16 hi/lo
    const int g1 = (M / 128) * (ITR / 128);
    gemm_mma<2, 1, 2><<<g1, 256, SMEM_F>>>(
        (const __nv_bfloat16*)xh, (const __nv_bfloat16*)xl,
        (const __nv_bfloat16*)gwh, (const __nv_bfloat16*)gwl,
        (const __nv_bfloat16*)uwh, (const __nv_bfloat16*)uwl,
        nullptr, (__nv_bfloat16*)ith, (__nv_bfloat16*)itl, ITR, HID);

    // down: out = it Dw^T  (fp32)
    const int g2 = (M / 128) * (HID / 128);
    gemm_mma<1, 0, 3><<<g2, 256, SMEM_D>>>(
        (const __nv_bfloat16*)ith, (const __nv_bfloat16*)itl,
        (const __nv_bfloat16*)dwh, (const __nv_bfloat16*)dwl,
        nullptr, nullptr,
        out, nullptr, nullptr, HID, ITR);
}

// round 15
// speedup vs baseline: 3.9010x; 1.0686x over previous
#include <cuda_runtime.h>
#include <cuda_bf16.h>
#include <stdint.h>
#include <math.h>

#define HID   2048
#define ITR   8192
#define MTOK  8192
#define NW ((size_t)ITR * (size_t)HID)

typedef uint32_t u32;
typedef unsigned long long u64;

// ---------------------------------------------------------------
// Static device scratch (no cudaMalloc allowed)
// ---------------------------------------------------------------
__device__ __align__(256) __nv_bfloat16 g_xh[(size_t)MTOK * HID];
__device__ __align__(256) __nv_bfloat16 g_xl[(size_t)MTOK * HID];
__device__ __align__(256) __nv_bfloat16 g_gwh[NW];
__device__ __align__(256) __nv_bfloat16 g_gwl[NW];
__device__ __align__(256) __nv_bfloat16 g_uwh[NW];
__device__ __align__(256) __nv_bfloat16 g_uwl[NW];
__device__ __align__(256) __nv_bfloat16 g_dwh[NW];
__device__ __align__(256) __nv_bfloat16 g_dwl[NW];
__device__ __align__(256) __nv_bfloat16 g_ith[(size_t)MTOK * ITR];
__device__ __align__(256) __nv_bfloat16 g_itl[(size_t)MTOK * ITR];

// ---------------------------------------------------------------
// PTX helpers (baseline sm_80/90 PTX only — nothing 'a'-gated)
// ---------------------------------------------------------------
__device__ __forceinline__ u32 smem_u32(const void* p) {
    u32 a;
    asm("{ .reg .u64 t; cvta.to.shared.u64 t, %1; cvt.u32.u64 %0, t; }" : "=r"(a) : "l"(p));
    return a;
}
__device__ __forceinline__ void cp16(u32 s, const void* g) {
    asm volatile("cp.async.cg.shared.global [%0], [%1], 16;" :: "r"(s), "l"(g) : "memory");
}
#define CP_COMMIT() asm volatile("cp.async.commit_group;" ::: "memory")
#define CP_WAIT(n)  asm volatile("cp.async.wait_group %0;" :: "n"(n) : "memory")

__device__ __forceinline__ void ldsm4(u32* r, u32 a) {
    asm volatile("ldmatrix.sync.aligned.m8n8.x4.shared.b16 {%0,%1,%2,%3}, [%4];"
                 : "=r"(r[0]), "=r"(r[1]), "=r"(r[2]), "=r"(r[3]) : "r"(a));
}
__device__ __forceinline__ void mma16816(float* d, const u32* a, const u32* b) {
    asm volatile("mma.sync.aligned.m16n8k16.row.col.f32.bf16.bf16.f32 "
                 "{%0,%1,%2,%3}, {%4,%5,%6,%7}, {%8,%9}, {%0,%1,%2,%3};"
                 : "+f"(d[0]), "+f"(d[1]), "+f"(d[2]), "+f"(d[3])
                 : "r"(a[0]), "r"(a[1]), "r"(a[2]), "r"(a[3]), "r"(b[0]), "r"(b[1]));
}

// ---------------------------------------------------------------
// Preprocessing
// ---------------------------------------------------------------
__device__ __forceinline__ void split2(float v, __nv_bfloat16& h, __nv_bfloat16& l) {
    h = __float2bfloat16_rn(v);
    l = __float2bfloat16_rn(v - __bfloat162float(h));
}

__global__ void xsplit_kernel(const float* __restrict__ x,
                              __nv_bfloat16* __restrict__ xh,
                              __nv_bfloat16* __restrict__ xl, long long n)
{
    long long j = ((long long)blockIdx.x * blockDim.x + threadIdx.x) * 4;
    if (j >= n) return;
    float4 v = *(const float4*)&x[j];
    __nv_bfloat16 hb[4], lb[4];
    split2(v.x, hb[0], lb[0]); split2(v.y, hb[1], lb[1]);
    split2(v.z, hb[2], lb[2]); split2(v.w, hb[3], lb[3]);
    *(uint2*)&xh[j] = *(const uint2*)hb;
    *(uint2*)&xl[j] = *(const uint2*)lb;
}

// Integer-exact Catmull-Rom: i = floor(j*(nc-1)/(n-1)), f = rem/(n-1).
struct SplineJob {
    const float* cp;
    __nv_bfloat16* wh;
    __nv_bfloat16* wl;
    int n_ctrl;
};

__global__ void spline3_kernel(SplineJob ja, SplineJob jb_, SplineJob jc, long long n)
{
    const SplineJob J = (blockIdx.y == 0) ? ja : (blockIdx.y == 1) ? jb_ : jc;
    const float* __restrict__ cp = J.cp;
    const long long j0 = ((long long)blockIdx.x * blockDim.x + threadIdx.x) * 8;
    if (j0 >= n) return;

    const u32 nm1 = (u32)(n - 1);
    const u32 ncm1 = (u32)(J.n_ctrl - 1);
    const u64 num = (u64)j0 * ncm1;
    u32 i = (u32)(num / nm1);
    u32 rem = (u32)(num - (u64)i * nm1);
    const float inv = 1.0f / (float)nm1;

    __align__(16) __nv_bfloat16 hb[8];
    __align__(16) __nv_bfloat16 lb[8];

#pragma unroll
    for (int e = 0; e < 8; e++) {
        int i1;
        float f;
        if (i >= ncm1) { i1 = (int)ncm1 - 1; f = 1.0f; }
        else           { i1 = (int)i;        f = (float)rem * inv; }

        const int i0 = i1 > 0 ? i1 - 1 : 0;
        const int i2 = i1 + 1;
        const int i3 = (u32)(i1 + 2) > ncm1 ? (int)ncm1 : i1 + 2;

        const float p0 = cp[i0], p1 = cp[i1], p2 = cp[i2], p3 = cp[i3];
        const float f2 = f * f;
        const float f3 = f2 * f;
        const float val = 0.5f * (2.0f * p1
                   + (p2 - p0) * f
                   + (2.0f * p0 - 5.0f * p1 + 4.0f * p2 - p3) * f2
                   + (3.0f * p1 - p0 - 3.0f * p2 + p3) * f3);
        split2(val, hb[e], lb[e]);

        rem += ncm1;
        if (rem >= nm1) { rem -= nm1; i++; }
    }
    *(uint4*)&J.wh[j0] = *(const uint4*)hb;
    *(uint4*)&J.wl[j0] = *(const uint4*)lb;
}

// ---------------------------------------------------------------
// Tensor-core NT GEMM via mma.sync (bf16, fp32 acc), split-bf16
// 3-pass: acc += Ah*Bh + Ah*Bl + Al*Bh
// Block 128x128(xNB), BK=64, 512 threads = 16 warps (4M x 4N),
// warp tile 32x32 -> small acc (32/64 regs) so 16 warps fit the RF.
// XOR-swizzled smem (128B rows, chunk c of row r at c^(r&7)).
// One __syncthreads per 64-deep K chunk.
// NB=2 + EPI=1: fused gate+up, SwiGLU in registers -> bf16 hi/lo out.
// NB=1 + EPI=0: plain GEMM -> fp32 out.
// ---------------------------------------------------------------
#define TILEB  (128 * 128)             // 16384 B per operand tile
#define GRP    8
#define NTHR   512

template <int NB, int EPI, int NS>
__global__ void __launch_bounds__(NTHR, 1)
gemm_mma(const __nv_bfloat16* __restrict__ Ah_,
         const __nv_bfloat16* __restrict__ Al_,
         const __nv_bfloat16* __restrict__ B0h_,
         const __nv_bfloat16* __restrict__ B0l_,
         const __nv_bfloat16* __restrict__ B1h_,
         const __nv_bfloat16* __restrict__ B1l_,
         float* __restrict__ Cf,
         __nv_bfloat16* __restrict__ Oh,
         __nv_bfloat16* __restrict__ Ol,
         int N, int K)
{
    constexpr u32 STAGEB = (u32)((2 + 2 * NB) * TILEB);
    extern __shared__ __align__(128) char sm[];
    const u32 sb = smem_u32(sm);
    const int tid  = threadIdx.x;
    const int lane = tid & 31;
    const int wid  = tid >> 5;       // 0..15
    const int wm   = wid & 3;        // 4 M slices of 32 rows
    const int wn   = wid >> 2;       // 4 N slices of 32 cols

    // raster swizzle: 8 bm-rows per group, bn sweeps within group
    const int tiles_n = N >> 7;
    const int per = GRP * tiles_n;
    const int grp = blockIdx.x / per;
    const int wit = blockIdx.x % per;
    const int bm = (grp * GRP + (wit % GRP)) * 128;
    const int bn = (wit / GRP) * 128;

    const int NC = K >> 6;

    float acc[NB][2][4][4];
#pragma unroll
    for (int nb = 0; nb < NB; nb++)
#pragma unroll
        for (int mi = 0; mi < 2; mi++)
#pragma unroll
            for (int ni = 0; ni < 4; ni++)
#pragma unroll
                for (int q = 0; q < 4; q++) acc[nb][mi][ni][q] = 0.0f;

    // cp.async coords: 128 rows x 8 chunks of 16B per tile = 1024 chunks;
    // 512 threads x 2 row-halves cover it.
    const int r0 = tid >> 3;         // 0..63
    const int ch = tid & 7;          // 0..7

    auto issue_stage = [&](int stg) {
        const u32 base = sb + (u32)(stg % NS) * STAGEB;
        const int k0 = stg * 64;
#pragma unroll
        for (int half = 0; half < 2; half++) {
            const int r = r0 + half * 64;
            const u32 so = base + (u32)r * 128 + (u32)((ch ^ (r & 7)) << 4);
            const size_t ga = (size_t)(bm + r) * K + k0 + ch * 8;
            const size_t gb = (size_t)(bn + r) * K + k0 + ch * 8;
            cp16(so + 0 * TILEB, Ah_ + ga);
            cp16(so + 1 * TILEB, Al_ + ga);
            cp16(so + 2 * TILEB, B0h_ + gb);
            cp16(so + 3 * TILEB, B0l_ + gb);
            if (NB == 2) {
                cp16(so + 4 * TILEB, B1h_ + gb);
                cp16(so + 5 * TILEB, B1l_ + gb);
            }
        }
    };

#pragma unroll
    for (int s = 0; s < NS - 1; s++) {
        if (s < NC) issue_stage(s);
        CP_COMMIT();
    }

    // ldmatrix coords
    const int alr = lane & 15;               // A row within 16
    const int ach = lane >> 4;               // A chunk half (0/1)
    const int blr4 = ((lane >> 4) & 1) * 8 + (lane & 7);  // B pair rows
    const int bch = (lane >> 3) & 1;         // B chunk half (0/1)

    for (int c = 0; c < NC; c++) {
        CP_WAIT(NS - 2);
        __syncthreads();

        const int pf = c + NS - 1;
        if (pf < NC) issue_stage(pf);
        CP_COMMIT();

        const u32 stb = sb + (u32)(c % NS) * STAGEB;

#pragma unroll
        for (int kk = 0; kk < 4; kk++) {
            u32 ah[2][4], al[2][4];
#pragma unroll
            for (int mi = 0; mi < 2; mi++) {
                const int row = wm * 32 + mi * 16 + alr;
                const int chv = kk * 2 + ach;
                const u32 ra = stb + (u32)row * 128 + (u32)((chv ^ (row & 7)) << 4);
                ldsm4(ah[mi], ra);
                ldsm4(al[mi], ra + TILEB);
            }
#pragma unroll
            for (int nb = 0; nb < NB; nb++) {
                u32 bh[4][2], bl[4][2];
#pragma unroll
                for (int p = 0; p < 2; p++) {
                    const int row = wn * 32 + p * 16 + blr4;
                    const int chv = kk * 2 + bch;
                    const u32 rb = stb + (u32)(2 + 2 * nb) * TILEB
                                 + (u32)row * 128 + (u32)((chv ^ (row & 7)) << 4);
                    u32 t[4];
                    ldsm4(t, rb);
                    bh[p * 2 + 0][0] = t[0]; bh[p * 2 + 0][1] = t[1];
                    bh[p * 2 + 1][0] = t[2]; bh[p * 2 + 1][1] = t[3];
                    ldsm4(t, rb + TILEB);
                    bl[p * 2 + 0][0] = t[0]; bl[p * 2 + 0][1] = t[1];
                    bl[p * 2 + 1][0] = t[2]; bl[p * 2 + 1][1] = t[3];
                }
#pragma unroll
                for (int mi = 0; mi < 2; mi++)
#pragma unroll
                    for (int ni = 0; ni < 4; ni++) {
                        mma16816(acc[nb][mi][ni], ah[mi], bh[ni]);
                        mma16816(acc[nb][mi][ni], ah[mi], bl[ni]);
                        mma16816(acc[nb][mi][ni], al[mi], bh[ni]);
                    }
            }
        }
    }

    // ---------------- epilogue ----------------
    const int er = lane >> 2;
    const int ec = (lane & 3) * 2;
#pragma unroll
    for (int mi = 0; mi < 2; mi++) {
#pragma unroll
        for (int ni = 0; ni < 4; ni++) {
            const int row = bm + wm * 32 + mi * 16 + er;
            const int col = bn + wn * 32 + ni * 8 + ec;
            if (EPI == 0) {
                const float* d = acc[0][mi][ni];
                *(float2*)&Cf[(size_t)row * N + col] = make_float2(d[0], d[1]);
                *(float2*)&Cf[(size_t)(row + 8) * N + col] = make_float2(d[2], d[3]);
            } else {
                const float* dg = acc[0][mi][ni];
                const float* du = acc[1][mi][ni];
#pragma unroll
                for (int h = 0; h < 2; h++) {
                    const size_t off = (size_t)(row + h * 8) * N + col;
                    float g0 = dg[h * 2 + 0], g1 = dg[h * 2 + 1];
                    float v0 = (g0 / (1.0f + expf(-g0))) * du[h * 2 + 0];
                    float v1 = (g1 / (1.0f + expf(-g1))) * du[h * 2 + 1];
                    __nv_bfloat16 h0, l0, h1, l1;
                    split2(v0, h0, l0);
                    split2(v1, h1, l1);
                    u32 ph = (u32)__bfloat16_as_ushort(h0) |
                             ((u32)__bfloat16_as_ushort(h1) << 16);
                    u32 pl = (u32)__bfloat16_as_ushort(l0) |
                             ((u32)__bfloat16_as_ushort(l1) << 16);
                    *(u32*)&Oh[off] = ph;
                    *(u32*)&Ol[off] = pl;
                }
            }
        }
    }
}

// ---------------------------------------------------------------
// Launch
// ---------------------------------------------------------------
extern "C" void kernel_launch(void* const* d_in, const int* in_sizes, int n_in,
                              void* d_out, int out_size)
{
    (void)n_in; (void)out_size;
    const float* x   = (const float*)d_in[0];
    const float* gcp = (const float*)d_in[1];
    const float* ucp = (const float*)d_in[2];
    const float* dcp = (const float*)d_in[3];
    float* out = (float*)d_out;

    const int M = in_sizes[0] / HID;   // 8192

    void *xh, *xl, *gwh, *gwl, *uwh, *uwl, *dwh, *dwl, *ith, *itl;
    cudaGetSymbolAddress(&xh, g_xh);   cudaGetSymbolAddress(&xl, g_xl);
    cudaGetSymbolAddress(&gwh, g_gwh); cudaGetSymbolAddress(&gwl, g_gwl);
    cudaGetSymbolAddress(&uwh, g_uwh); cudaGetSymbolAddress(&uwl, g_uwl);
    cudaGetSymbolAddress(&dwh, g_dwh); cudaGetSymbolAddress(&dwl, g_dwl);
    cudaGetSymbolAddress(&ith, g_ith); cudaGetSymbolAddress(&itl, g_itl);

    constexpr int SMEM_F = 2 * 6 * TILEB;   // NS=2, 6 tiles: 196608
    constexpr int SMEM_D = 3 * 4 * TILEB;   // NS=3, 4 tiles: 196608
    cudaFuncSetAttribute(gemm_mma<2, 1, 2>,
                         cudaFuncAttributeMaxDynamicSharedMemorySize, SMEM_F);
    cudaFuncSetAttribute(gemm_mma<1, 0, 3>,
                         cudaFuncAttributeMaxDynamicSharedMemorySize, SMEM_D);

    long long nX = (long long)M * HID;
    xsplit_kernel<<<(int)((nX / 4 + 255) / 256), 256>>>(x, (__nv_bfloat16*)xh,
                                                        (__nv_bfloat16*)xl, nX);
    long long nw = (long long)NW;
    SplineJob jg = { gcp, (__nv_bfloat16*)gwh, (__nv_bfloat16*)gwl, in_sizes[1] };
    SplineJob ju = { ucp, (__nv_bfloat16*)uwh, (__nv_bfloat16*)uwl, in_sizes[2] };
    SplineJob jd = { dcp, (__nv_bfloat16*)dwh, (__nv_bfloat16*)dwl, in_sizes[3] };
    dim3 sg((u32)((nw / 8 + 255) / 256), 3);
    spline3_kernel<<<sg, 256>>>(jg, ju, jd, nw);

    // fused: it = silu(X Gw^T) * (X Uw^T)  -> bf16 hi/lo
    const int g1 = (M / 128) * (ITR / 128);
    gemm_mma<2, 1, 2><<<g1, NTHR, SMEM_F>>>(
        (const __nv_bfloat16*)xh, (const __nv_bfloat16*)xl,
        (const __nv_bfloat16*)gwh, (const __nv_bfloat16*)gwl,
        (const __nv_bfloat16*)uwh, (const __nv_bfloat16*)uwl,
        nullptr, (__nv_bfloat16*)ith, (__nv_bfloat16*)itl, ITR, HID);

    // down: out = it Dw^T  (fp32)
    const int g2 = (M / 128) * (HID / 128);
    gemm_mma<1, 0, 3><<<g2, NTHR, SMEM_D>>>(
        (const __nv_bfloat16*)ith, (const __nv_bfloat16*)itl,
        (const __nv_bfloat16*)dwh, (const __nv_bfloat16*)dwl,
        nullptr, nullptr,
        out, nullptr, nullptr, HID, ITR);
}